// round 1
// baseline (speedup 1.0000x reference)
#include <cuda_runtime.h>
#include <cuda_bf16.h>
#include <math.h>

#define D_MODEL 1024
#define D_FFN   2048
#define NE      8
#define T_TOKENS 4096
#define NPAIR   8192   // T_TOKENS * TOP_K

// ---------------- scratch (device globals; no allocations allowed) ----------
__device__ int   g_cnt[NE];
__device__ int   g_pid[NE * NPAIR];
__device__ float g_wt [NE * NPAIR];
__device__ float g_H  [(size_t)NPAIR * D_FFN];    // SwiGLU hidden per (token,k) pair
__device__ float g_Y  [(size_t)NPAIR * D_MODEL];  // weighted down-proj per pair

// ---------------- packed f32x2 helpers (sm_100+) ----------------------------
__device__ __forceinline__ unsigned long long pack2(float lo, float hi) {
    unsigned long long r;
    asm("mov.b64 %0, {%1, %2};" : "=l"(r) : "f"(lo), "f"(hi));
    return r;
}
__device__ __forceinline__ void unpack2(unsigned long long p, float& lo, float& hi) {
    asm("mov.b64 {%0, %1}, %2;" : "=f"(lo), "=f"(hi) : "l"(p));
}
__device__ __forceinline__ void fma2(unsigned long long& d,
                                     unsigned long long a, unsigned long long b) {
    asm("fma.rn.f32x2 %0, %1, %2, %0;" : "+l"(d) : "l"(a), "l"(b));
}

// ---------------- kernel 0: reset counters ----------------------------------
__global__ void zero_cnt_kernel() {
    if (threadIdx.x < NE) g_cnt[threadIdx.x] = 0;
}

// ---------------- kernel 1: router ------------------------------------------
// One block (256 thr = 8 warps) per token; warp e computes logit for expert e.
__global__ __launch_bounds__(256) void router_kernel(const float* __restrict__ x,
                                                     const float* __restrict__ wr) {
    const int t = blockIdx.x;
    const int warp = threadIdx.x >> 5, lane = threadIdx.x & 31;
    __shared__ float logits[NE];
    const float* xr = x + (size_t)t * D_MODEL;
    const float* w  = wr + (size_t)warp * D_MODEL;
    float s = 0.f;
    #pragma unroll 8
    for (int i = lane; i < D_MODEL; i += 32) s += xr[i] * w[i];
    #pragma unroll
    for (int o = 16; o; o >>= 1) s += __shfl_xor_sync(0xffffffffu, s, o);
    if (lane == 0) logits[warp] = s;
    __syncthreads();
    if (threadIdx.x == 0) {
        int i0 = 0; float v0 = logits[0];
        #pragma unroll
        for (int e = 1; e < NE; e++) if (logits[e] > v0) { v0 = logits[e]; i0 = e; }
        int i1 = -1; float v1 = -1e30f;
        #pragma unroll
        for (int e = 0; e < NE; e++)
            if (e != i0 && logits[e] > v1) { v1 = logits[e]; i1 = e; }
        float ex = __expf(v1 - v0);            // <= 1
        float w0 = 1.f / (1.f + ex);
        float w1 = ex  / (1.f + ex);
        int s0 = atomicAdd(&g_cnt[i0], 1);
        g_pid[i0 * NPAIR + s0] = t * 2;     g_wt[i0 * NPAIR + s0] = w0;
        int s1 = atomicAdd(&g_cnt[i1], 1);
        g_pid[i1 * NPAIR + s1] = t * 2 + 1; g_wt[i1 * NPAIR + s1] = w1;
    }
}

// ---------------- kernel 2: grouped gate+up GEMM + SwiGLU -------------------
// C tile 64x64, K-step 16, 256 threads, double-buffered smem, f32x2 FMAs.
// A = gathered x rows (by token), B = w_gate / w_up rows (K-contiguous).
__global__ __launch_bounds__(256) void gateup_kernel(const float* __restrict__ x,
                                                     const float* __restrict__ wg,
                                                     const float* __restrict__ wu) {
    const int e  = blockIdx.z;
    const int ne = g_cnt[e];
    const int m0 = blockIdx.x * 64;
    if (m0 >= ne) return;
    const int n0 = blockIdx.y * 64;

    __shared__ float As [2][16][68];
    __shared__ float Bgs[2][16][68];
    __shared__ float Bus[2][16][68];
    __shared__ int   s_pid[64];

    const int tid = threadIdx.x;
    if (tid < 64) {
        int r = m0 + tid;
        s_pid[tid] = g_pid[e * NPAIR + (r < ne ? r : m0)];
    }
    __syncthreads();

    const int lrow = tid >> 2;          // 0..63
    const int lk4  = (tid & 3) * 4;     // 0,4,8,12
    const int tok  = s_pid[lrow] >> 1;
    const float* aptr = x  + (size_t)tok * D_MODEL + lk4;
    const float* gptr = wg + (size_t)e * D_FFN * D_MODEL + (size_t)(n0 + lrow) * D_MODEL + lk4;
    const float* uptr = wu + (size_t)e * D_FFN * D_MODEL + (size_t)(n0 + lrow) * D_MODEL + lk4;
    const int ty = tid >> 4, tx = tid & 15;

    float4 ra = *(const float4*)aptr;
    float4 rg = *(const float4*)gptr;
    float4 ru = *(const float4*)uptr;

#define GU_STORE(B) do {                                                        \
        As [B][lk4+0][lrow]=ra.x; As [B][lk4+1][lrow]=ra.y;                     \
        As [B][lk4+2][lrow]=ra.z; As [B][lk4+3][lrow]=ra.w;                     \
        Bgs[B][lk4+0][lrow]=rg.x; Bgs[B][lk4+1][lrow]=rg.y;                     \
        Bgs[B][lk4+2][lrow]=rg.z; Bgs[B][lk4+3][lrow]=rg.w;                     \
        Bus[B][lk4+0][lrow]=ru.x; Bus[B][lk4+1][lrow]=ru.y;                     \
        Bus[B][lk4+2][lrow]=ru.z; Bus[B][lk4+3][lrow]=ru.w; } while (0)

    GU_STORE(0);
    __syncthreads();

    unsigned long long accg[4][2] = {{0ull,0ull},{0ull,0ull},{0ull,0ull},{0ull,0ull}};
    unsigned long long accu[4][2] = {{0ull,0ull},{0ull,0ull},{0ull,0ull},{0ull,0ull}};

    const int NT = D_MODEL / 16;    // 64
    for (int kt = 0; kt < NT; ++kt) {
        const int buf = kt & 1;
        const bool nxt = (kt + 1) < NT;
        if (nxt) {
            const int off = (kt + 1) * 16;
            ra = *(const float4*)(aptr + off);
            rg = *(const float4*)(gptr + off);
            ru = *(const float4*)(uptr + off);
        }
        #pragma unroll
        for (int k = 0; k < 16; ++k) {
            float4 av  = *(const float4*)&As [buf][k][ty * 4];
            float4 bgv = *(const float4*)&Bgs[buf][k][tx * 4];
            float4 buv = *(const float4*)&Bus[buf][k][tx * 4];
            unsigned long long a0 = pack2(av.x, av.x), a1 = pack2(av.y, av.y);
            unsigned long long a2 = pack2(av.z, av.z), a3 = pack2(av.w, av.w);
            unsigned long long bg0 = pack2(bgv.x, bgv.y), bg1 = pack2(bgv.z, bgv.w);
            unsigned long long bu0 = pack2(buv.x, buv.y), bu1 = pack2(buv.z, buv.w);
            fma2(accg[0][0], a0, bg0); fma2(accg[0][1], a0, bg1);
            fma2(accg[1][0], a1, bg0); fma2(accg[1][1], a1, bg1);
            fma2(accg[2][0], a2, bg0); fma2(accg[2][1], a2, bg1);
            fma2(accg[3][0], a3, bg0); fma2(accg[3][1], a3, bg1);
            fma2(accu[0][0], a0, bu0); fma2(accu[0][1], a0, bu1);
            fma2(accu[1][0], a1, bu0); fma2(accu[1][1], a1, bu1);
            fma2(accu[2][0], a2, bu0); fma2(accu[2][1], a2, bu1);
            fma2(accu[3][0], a3, bu0); fma2(accu[3][1], a3, bu1);
        }
        if (nxt) GU_STORE(buf ^ 1);
        __syncthreads();
    }
#undef GU_STORE

    #pragma unroll
    for (int i = 0; i < 4; ++i) {
        const int mr = ty * 4 + i;
        const int r  = m0 + mr;
        if (r < ne) {
            const int pid = s_pid[mr];
            float g0,g1,g2,g3,u0,u1,u2,u3;
            unpack2(accg[i][0], g0, g1); unpack2(accg[i][1], g2, g3);
            unpack2(accu[i][0], u0, u1); unpack2(accu[i][1], u2, u3);
            float4 hv;
            hv.x = (g0 / (1.f + __expf(-g0))) * u0;
            hv.y = (g1 / (1.f + __expf(-g1))) * u1;
            hv.z = (g2 / (1.f + __expf(-g2))) * u2;
            hv.w = (g3 / (1.f + __expf(-g3))) * u3;
            *(float4*)&g_H[(size_t)pid * D_FFN + n0 + tx * 4] = hv;
        }
    }
}

// ---------------- kernel 3: grouped down GEMM (weight folded) ---------------
__global__ __launch_bounds__(256) void down_kernel(const float* __restrict__ wd) {
    const int e  = blockIdx.z;
    const int ne = g_cnt[e];
    const int m0 = blockIdx.x * 64;
    if (m0 >= ne) return;
    const int n0 = blockIdx.y * 64;

    __shared__ float As[2][16][68];
    __shared__ float Bs[2][16][68];
    __shared__ int   s_pid[64];
    __shared__ float s_w[64];

    const int tid = threadIdx.x;
    if (tid < 64) {
        int r  = m0 + tid;
        int rr = (r < ne) ? r : m0;
        s_pid[tid] = g_pid[e * NPAIR + rr];
        s_w[tid]   = g_wt [e * NPAIR + rr];
    }
    __syncthreads();

    const int lrow = tid >> 2;
    const int lk4  = (tid & 3) * 4;
    const int pidA = s_pid[lrow];
    const float* aptr = g_H + (size_t)pidA * D_FFN + lk4;
    const float* bptr = wd  + (size_t)e * D_MODEL * D_FFN + (size_t)(n0 + lrow) * D_FFN + lk4;
    const int ty = tid >> 4, tx = tid & 15;

    float4 ra = *(const float4*)aptr;
    float4 rb = *(const float4*)bptr;

#define DN_STORE(B) do {                                                        \
        As[B][lk4+0][lrow]=ra.x; As[B][lk4+1][lrow]=ra.y;                       \
        As[B][lk4+2][lrow]=ra.z; As[B][lk4+3][lrow]=ra.w;                       \
        Bs[B][lk4+0][lrow]=rb.x; Bs[B][lk4+1][lrow]=rb.y;                       \
        Bs[B][lk4+2][lrow]=rb.z; Bs[B][lk4+3][lrow]=rb.w; } while (0)

    DN_STORE(0);
    __syncthreads();

    unsigned long long acc[4][2] = {{0ull,0ull},{0ull,0ull},{0ull,0ull},{0ull,0ull}};

    const int NT = D_FFN / 16;      // 128
    for (int kt = 0; kt < NT; ++kt) {
        const int buf = kt & 1;
        const bool nxt = (kt + 1) < NT;
        if (nxt) {
            const int off = (kt + 1) * 16;
            ra = *(const float4*)(aptr + off);
            rb = *(const float4*)(bptr + off);
        }
        #pragma unroll
        for (int k = 0; k < 16; ++k) {
            float4 av = *(const float4*)&As[buf][k][ty * 4];
            float4 bv = *(const float4*)&Bs[buf][k][tx * 4];
            unsigned long long a0 = pack2(av.x, av.x), a1 = pack2(av.y, av.y);
            unsigned long long a2 = pack2(av.z, av.z), a3 = pack2(av.w, av.w);
            unsigned long long b0 = pack2(bv.x, bv.y), b1 = pack2(bv.z, bv.w);
            fma2(acc[0][0], a0, b0); fma2(acc[0][1], a0, b1);
            fma2(acc[1][0], a1, b0); fma2(acc[1][1], a1, b1);
            fma2(acc[2][0], a2, b0); fma2(acc[2][1], a2, b1);
            fma2(acc[3][0], a3, b0); fma2(acc[3][1], a3, b1);
        }
        if (nxt) DN_STORE(buf ^ 1);
        __syncthreads();
    }
#undef DN_STORE

    #pragma unroll
    for (int i = 0; i < 4; ++i) {
        const int mr = ty * 4 + i;
        const int r  = m0 + mr;
        if (r < ne) {
            const int pid = s_pid[mr];
            const float w = s_w[mr];
            float y0,y1,y2,y3;
            unpack2(acc[i][0], y0, y1); unpack2(acc[i][1], y2, y3);
            float4 yv = { y0 * w, y1 * w, y2 * w, y3 * w };
            *(float4*)&g_Y[(size_t)pid * D_MODEL + n0 + tx * 4] = yv;
        }
    }
}

// ---------------- kernel 4: combine pairs + LayerNorm -----------------------
__global__ __launch_bounds__(256) void combine_ln_kernel(const float* __restrict__ gamma,
                                                         const float* __restrict__ beta,
                                                         float* __restrict__ out) {
    const int t   = blockIdx.x;
    const int tid = threadIdx.x;
    const float4 a = ((const float4*)(g_Y + (size_t)(2 * t)     * D_MODEL))[tid];
    const float4 b = ((const float4*)(g_Y + (size_t)(2 * t + 1) * D_MODEL))[tid];
    float4 v = { a.x + b.x, a.y + b.y, a.z + b.z, a.w + b.w };

    float s  = v.x + v.y + v.z + v.w;
    float sq = v.x * v.x + v.y * v.y + v.z * v.z + v.w * v.w;
    #pragma unroll
    for (int o = 16; o; o >>= 1) {
        s  += __shfl_xor_sync(0xffffffffu, s,  o);
        sq += __shfl_xor_sync(0xffffffffu, sq, o);
    }
    __shared__ float rs_[8], rq_[8];
    __shared__ float s_mu, s_rs;
    if ((tid & 31) == 0) { rs_[tid >> 5] = s; rq_[tid >> 5] = sq; }
    __syncthreads();
    if (tid == 0) {
        float S = 0.f, Q = 0.f;
        #pragma unroll
        for (int i = 0; i < 8; i++) { S += rs_[i]; Q += rq_[i]; }
        float mu  = S / (float)D_MODEL;
        float var = Q / (float)D_MODEL - mu * mu;
        s_mu = mu;
        s_rs = rsqrtf(var + 1e-5f);
    }
    __syncthreads();
    const float mu = s_mu, rs = s_rs;
    const float4 gg = ((const float4*)gamma)[tid];
    const float4 bb = ((const float4*)beta)[tid];
    float4 o;
    o.x = (v.x - mu) * rs * gg.x + bb.x;
    o.y = (v.y - mu) * rs * gg.y + bb.y;
    o.z = (v.z - mu) * rs * gg.z + bb.z;
    o.w = (v.w - mu) * rs * gg.w + bb.w;
    ((float4*)out)[(size_t)t * (D_MODEL / 4) + tid] = o;
}

// ---------------- launch -----------------------------------------------------
extern "C" void kernel_launch(void* const* d_in, const int* in_sizes, int n_in,
                              void* d_out, int out_size) {
    const float* x     = (const float*)d_in[0];
    const float* wr    = (const float*)d_in[1];
    const float* wg    = (const float*)d_in[2];
    const float* wu    = (const float*)d_in[3];
    const float* wd    = (const float*)d_in[4];
    const float* gamma = (const float*)d_in[5];
    const float* beta  = (const float*)d_in[6];
    float* out = (float*)d_out;

    zero_cnt_kernel<<<1, 32>>>();
    router_kernel<<<T_TOKENS, 256>>>(x, wr);
    dim3 g2(NPAIR / 64, D_FFN / 64, NE);
    gateup_kernel<<<g2, 256>>>(x, wg, wu);
    dim3 g3(NPAIR / 64, D_MODEL / 64, NE);
    down_kernel<<<g3, 256>>>(wd);
    combine_ln_kernel<<<T_TOKENS, 256>>>(gamma, beta, out);
}

// round 2
// speedup vs baseline: 1.2272x; 1.2272x over previous
#include <cuda_runtime.h>
#include <cuda_bf16.h>
#include <math.h>

#define D_MODEL 1024
#define D_FFN   2048
#define NE      8
#define T_TOKENS 4096
#define NPAIR   8192   // T_TOKENS * TOP_K

// ---------------- scratch (device globals; no allocations allowed) ----------
__device__ int   g_cnt[NE];
__device__ int   g_pid[NE * NPAIR];
__device__ float g_wt [NE * NPAIR];
__device__ float g_H  [(size_t)NPAIR * D_FFN];    // SwiGLU hidden per (token,k) pair
__device__ float g_Y  [(size_t)NPAIR * D_MODEL];  // weighted down-proj per pair

// ---------------- packed f32x2 helpers (sm_100+) ----------------------------
__device__ __forceinline__ unsigned long long pack2(float lo, float hi) {
    unsigned long long r;
    asm("mov.b64 %0, {%1, %2};" : "=l"(r) : "f"(lo), "f"(hi));
    return r;
}
__device__ __forceinline__ void unpack2(unsigned long long p, float& lo, float& hi) {
    asm("mov.b64 {%0, %1}, %2;" : "=f"(lo), "=f"(hi) : "l"(p));
}
__device__ __forceinline__ void fma2(unsigned long long& d,
                                     unsigned long long a, unsigned long long b) {
    asm("fma.rn.f32x2 %0, %1, %2, %0;" : "+l"(d) : "l"(a), "l"(b));
}

// ---------------- kernel 0: reset counters ----------------------------------
__global__ void zero_cnt_kernel() {
    if (threadIdx.x < NE) g_cnt[threadIdx.x] = 0;
}

// ---------------- kernel 1: router ------------------------------------------
__global__ __launch_bounds__(256) void router_kernel(const float* __restrict__ x,
                                                     const float* __restrict__ wr) {
    const int t = blockIdx.x;
    const int warp = threadIdx.x >> 5, lane = threadIdx.x & 31;
    __shared__ float logits[NE];
    const float* xr = x + (size_t)t * D_MODEL;
    const float* w  = wr + (size_t)warp * D_MODEL;
    float s = 0.f;
    #pragma unroll 8
    for (int i = lane; i < D_MODEL; i += 32) s += xr[i] * w[i];
    #pragma unroll
    for (int o = 16; o; o >>= 1) s += __shfl_xor_sync(0xffffffffu, s, o);
    if (lane == 0) logits[warp] = s;
    __syncthreads();
    if (threadIdx.x == 0) {
        int i0 = 0; float v0 = logits[0];
        #pragma unroll
        for (int e = 1; e < NE; e++) if (logits[e] > v0) { v0 = logits[e]; i0 = e; }
        int i1 = -1; float v1 = -1e30f;
        #pragma unroll
        for (int e = 0; e < NE; e++)
            if (e != i0 && logits[e] > v1) { v1 = logits[e]; i1 = e; }
        float ex = __expf(v1 - v0);            // <= 1
        float w0 = 1.f / (1.f + ex);
        float w1 = ex  / (1.f + ex);
        int s0 = atomicAdd(&g_cnt[i0], 1);
        g_pid[i0 * NPAIR + s0] = t * 2;     g_wt[i0 * NPAIR + s0] = w0;
        int s1 = atomicAdd(&g_cnt[i1], 1);
        g_pid[i1 * NPAIR + s1] = t * 2 + 1; g_wt[i1 * NPAIR + s1] = w1;
    }
}

// ---------------- kernel 2: grouped gate+up GEMM + SwiGLU -------------------
// C tile 128(m) x 64(f), computing BOTH gate and up. 256 threads, each thread
// owns 8(m) x 4(f) for gate and up. K-step 16, double-buffered smem.
// smem bytes per 64 FMAs per thread = 64B  (1 B/FMA).
__global__ __launch_bounds__(256, 2) void gateup_kernel(const float* __restrict__ x,
                                                        const float* __restrict__ wg,
                                                        const float* __restrict__ wu) {
    const int e  = blockIdx.z;
    const int ne = g_cnt[e];
    const int m0 = blockIdx.x * 128;
    if (m0 >= ne) return;
    const int n0 = blockIdx.y * 64;

    __shared__ float As [2][16][132];
    __shared__ float Bgs[2][16][68];
    __shared__ float Bus[2][16][68];
    __shared__ int   s_pid[128];

    const int tid = threadIdx.x;
    if (tid < 128) {
        int r = m0 + tid;
        s_pid[tid] = g_pid[e * NPAIR + (r < ne ? r : m0)];
    }
    __syncthreads();

    const int lr  = tid >> 2;           // 0..63
    const int lk4 = (tid & 3) * 4;      // 0,4,8,12
    const int tok0 = s_pid[lr]      >> 1;
    const int tok1 = s_pid[lr + 64] >> 1;
    const float* a0p = x  + (size_t)tok0 * D_MODEL + lk4;
    const float* a1p = x  + (size_t)tok1 * D_MODEL + lk4;
    const float* gp  = wg + (size_t)e * D_FFN * D_MODEL + (size_t)(n0 + lr) * D_MODEL + lk4;
    const float* up  = wu + (size_t)e * D_FFN * D_MODEL + (size_t)(n0 + lr) * D_MODEL + lk4;
    const int ty = tid >> 4, tx = tid & 15;

    float4 ra0 = *(const float4*)a0p;
    float4 ra1 = *(const float4*)a1p;
    float4 rg  = *(const float4*)gp;
    float4 ru  = *(const float4*)up;

#define GU_STORE(B) do {                                                       \
        As [B][lk4+0][lr]    = ra0.x; As [B][lk4+1][lr]    = ra0.y;            \
        As [B][lk4+2][lr]    = ra0.z; As [B][lk4+3][lr]    = ra0.w;            \
        As [B][lk4+0][lr+64] = ra1.x; As [B][lk4+1][lr+64] = ra1.y;            \
        As [B][lk4+2][lr+64] = ra1.z; As [B][lk4+3][lr+64] = ra1.w;            \
        Bgs[B][lk4+0][lr] = rg.x; Bgs[B][lk4+1][lr] = rg.y;                    \
        Bgs[B][lk4+2][lr] = rg.z; Bgs[B][lk4+3][lr] = rg.w;                    \
        Bus[B][lk4+0][lr] = ru.x; Bus[B][lk4+1][lr] = ru.y;                    \
        Bus[B][lk4+2][lr] = ru.z; Bus[B][lk4+3][lr] = ru.w; } while (0)

    GU_STORE(0);
    __syncthreads();

    unsigned long long accg[8][2];
    unsigned long long accu[8][2];
    #pragma unroll
    for (int i = 0; i < 8; ++i) {
        accg[i][0] = accg[i][1] = 0ull;
        accu[i][0] = accu[i][1] = 0ull;
    }

    const int NT = D_MODEL / 16;    // 64
    for (int kt = 0; kt < NT; ++kt) {
        const int buf = kt & 1;
        const bool nxt = (kt + 1) < NT;
        if (nxt) {
            const int off = (kt + 1) * 16;
            ra0 = *(const float4*)(a0p + off);
            ra1 = *(const float4*)(a1p + off);
            rg  = *(const float4*)(gp  + off);
            ru  = *(const float4*)(up  + off);
        }
        #pragma unroll
        for (int k = 0; k < 16; ++k) {
            float4 al  = *(const float4*)&As [buf][k][ty * 8];
            float4 ah  = *(const float4*)&As [buf][k][ty * 8 + 4];
            float4 bgv = *(const float4*)&Bgs[buf][k][tx * 4];
            float4 buv = *(const float4*)&Bus[buf][k][tx * 4];
            unsigned long long bg01 = pack2(bgv.x, bgv.y), bg23 = pack2(bgv.z, bgv.w);
            unsigned long long bu01 = pack2(buv.x, buv.y), bu23 = pack2(buv.z, buv.w);
            unsigned long long am[8];
            am[0] = pack2(al.x, al.x); am[1] = pack2(al.y, al.y);
            am[2] = pack2(al.z, al.z); am[3] = pack2(al.w, al.w);
            am[4] = pack2(ah.x, ah.x); am[5] = pack2(ah.y, ah.y);
            am[6] = pack2(ah.z, ah.z); am[7] = pack2(ah.w, ah.w);
            #pragma unroll
            for (int i = 0; i < 8; ++i) {
                fma2(accg[i][0], am[i], bg01); fma2(accg[i][1], am[i], bg23);
                fma2(accu[i][0], am[i], bu01); fma2(accu[i][1], am[i], bu23);
            }
        }
        if (nxt) GU_STORE(buf ^ 1);
        __syncthreads();
    }
#undef GU_STORE

    #pragma unroll
    for (int i = 0; i < 8; ++i) {
        const int mr = ty * 8 + i;
        const int r  = m0 + mr;
        if (r < ne) {
            const int pid = s_pid[mr];
            float g0,g1,g2,g3,u0,u1,u2,u3;
            unpack2(accg[i][0], g0, g1); unpack2(accg[i][1], g2, g3);
            unpack2(accu[i][0], u0, u1); unpack2(accu[i][1], u2, u3);
            float4 hv;
            hv.x = (g0 / (1.f + __expf(-g0))) * u0;
            hv.y = (g1 / (1.f + __expf(-g1))) * u1;
            hv.z = (g2 / (1.f + __expf(-g2))) * u2;
            hv.w = (g3 / (1.f + __expf(-g3))) * u3;
            *(float4*)&g_H[(size_t)pid * D_FFN + n0 + tx * 4] = hv;
        }
    }
}

// ---------------- kernel 3: grouped down GEMM (weight folded) ---------------
// C tile 128(m) x 128(n), 256 threads, 8x8 per thread. 1 B/FMA of smem.
__global__ __launch_bounds__(256, 2) void down_kernel(const float* __restrict__ wd) {
    const int e  = blockIdx.z;
    const int ne = g_cnt[e];
    const int m0 = blockIdx.x * 128;
    if (m0 >= ne) return;
    const int n0 = blockIdx.y * 128;

    __shared__ float As[2][16][132];
    __shared__ float Bs[2][16][132];
    __shared__ int   s_pid[128];
    __shared__ float s_w[128];

    const int tid = threadIdx.x;
    if (tid < 128) {
        int r  = m0 + tid;
        int rr = (r < ne) ? r : m0;
        s_pid[tid] = g_pid[e * NPAIR + rr];
        s_w[tid]   = g_wt [e * NPAIR + rr];
    }
    __syncthreads();

    const int lr  = tid >> 2;           // 0..63
    const int lk4 = (tid & 3) * 4;
    const int pa0 = s_pid[lr];
    const int pa1 = s_pid[lr + 64];
    const float* a0p = g_H + (size_t)pa0 * D_FFN + lk4;
    const float* a1p = g_H + (size_t)pa1 * D_FFN + lk4;
    const float* b0p = wd + (size_t)e * D_MODEL * D_FFN + (size_t)(n0 + lr)      * D_FFN + lk4;
    const float* b1p = wd + (size_t)e * D_MODEL * D_FFN + (size_t)(n0 + lr + 64) * D_FFN + lk4;
    const int ty = tid >> 4, tx = tid & 15;

    float4 ra0 = *(const float4*)a0p;
    float4 ra1 = *(const float4*)a1p;
    float4 rb0 = *(const float4*)b0p;
    float4 rb1 = *(const float4*)b1p;

#define DN_STORE(B) do {                                                       \
        As[B][lk4+0][lr]    = ra0.x; As[B][lk4+1][lr]    = ra0.y;              \
        As[B][lk4+2][lr]    = ra0.z; As[B][lk4+3][lr]    = ra0.w;              \
        As[B][lk4+0][lr+64] = ra1.x; As[B][lk4+1][lr+64] = ra1.y;              \
        As[B][lk4+2][lr+64] = ra1.z; As[B][lk4+3][lr+64] = ra1.w;              \
        Bs[B][lk4+0][lr]    = rb0.x; Bs[B][lk4+1][lr]    = rb0.y;              \
        Bs[B][lk4+2][lr]    = rb0.z; Bs[B][lk4+3][lr]    = rb0.w;              \
        Bs[B][lk4+0][lr+64] = rb1.x; Bs[B][lk4+1][lr+64] = rb1.y;              \
        Bs[B][lk4+2][lr+64] = rb1.z; Bs[B][lk4+3][lr+64] = rb1.w; } while (0)

    DN_STORE(0);
    __syncthreads();

    unsigned long long acc[8][4];
    #pragma unroll
    for (int i = 0; i < 8; ++i)
        acc[i][0] = acc[i][1] = acc[i][2] = acc[i][3] = 0ull;

    const int NT = D_FFN / 16;      // 128
    for (int kt = 0; kt < NT; ++kt) {
        const int buf = kt & 1;
        const bool nxt = (kt + 1) < NT;
        if (nxt) {
            const int off = (kt + 1) * 16;
            ra0 = *(const float4*)(a0p + off);
            ra1 = *(const float4*)(a1p + off);
            rb0 = *(const float4*)(b0p + off);
            rb1 = *(const float4*)(b1p + off);
        }
        #pragma unroll
        for (int k = 0; k < 16; ++k) {
            float4 al = *(const float4*)&As[buf][k][ty * 8];
            float4 ah = *(const float4*)&As[buf][k][ty * 8 + 4];
            float4 bl = *(const float4*)&Bs[buf][k][tx * 8];
            float4 bh = *(const float4*)&Bs[buf][k][tx * 8 + 4];
            unsigned long long b01 = pack2(bl.x, bl.y), b23 = pack2(bl.z, bl.w);
            unsigned long long b45 = pack2(bh.x, bh.y), b67 = pack2(bh.z, bh.w);
            unsigned long long am[8];
            am[0] = pack2(al.x, al.x); am[1] = pack2(al.y, al.y);
            am[2] = pack2(al.z, al.z); am[3] = pack2(al.w, al.w);
            am[4] = pack2(ah.x, ah.x); am[5] = pack2(ah.y, ah.y);
            am[6] = pack2(ah.z, ah.z); am[7] = pack2(ah.w, ah.w);
            #pragma unroll
            for (int i = 0; i < 8; ++i) {
                fma2(acc[i][0], am[i], b01); fma2(acc[i][1], am[i], b23);
                fma2(acc[i][2], am[i], b45); fma2(acc[i][3], am[i], b67);
            }
        }
        if (nxt) DN_STORE(buf ^ 1);
        __syncthreads();
    }
#undef DN_STORE

    #pragma unroll
    for (int i = 0; i < 8; ++i) {
        const int mr = ty * 8 + i;
        const int r  = m0 + mr;
        if (r < ne) {
            const int pid = s_pid[mr];
            const float w = s_w[mr];
            float y0,y1,y2,y3,y4,y5,y6,y7;
            unpack2(acc[i][0], y0, y1); unpack2(acc[i][1], y2, y3);
            unpack2(acc[i][2], y4, y5); unpack2(acc[i][3], y6, y7);
            float4 v0 = { y0 * w, y1 * w, y2 * w, y3 * w };
            float4 v1 = { y4 * w, y5 * w, y6 * w, y7 * w };
            float* dst = &g_Y[(size_t)pid * D_MODEL + n0 + tx * 8];
            *(float4*)dst       = v0;
            *(float4*)(dst + 4) = v1;
        }
    }
}

// ---------------- kernel 4: combine pairs + LayerNorm -----------------------
__global__ __launch_bounds__(256) void combine_ln_kernel(const float* __restrict__ gamma,
                                                         const float* __restrict__ beta,
                                                         float* __restrict__ out) {
    const int t   = blockIdx.x;
    const int tid = threadIdx.x;
    const float4 a = ((const float4*)(g_Y + (size_t)(2 * t)     * D_MODEL))[tid];
    const float4 b = ((const float4*)(g_Y + (size_t)(2 * t + 1) * D_MODEL))[tid];
    float4 v = { a.x + b.x, a.y + b.y, a.z + b.z, a.w + b.w };

    float s  = v.x + v.y + v.z + v.w;
    float sq = v.x * v.x + v.y * v.y + v.z * v.z + v.w * v.w;
    #pragma unroll
    for (int o = 16; o; o >>= 1) {
        s  += __shfl_xor_sync(0xffffffffu, s,  o);
        sq += __shfl_xor_sync(0xffffffffu, sq, o);
    }
    __shared__ float rs_[8], rq_[8];
    __shared__ float s_mu, s_rs;
    if ((tid & 31) == 0) { rs_[tid >> 5] = s; rq_[tid >> 5] = sq; }
    __syncthreads();
    if (tid == 0) {
        float S = 0.f, Q = 0.f;
        #pragma unroll
        for (int i = 0; i < 8; i++) { S += rs_[i]; Q += rq_[i]; }
        float mu  = S / (float)D_MODEL;
        float var = Q / (float)D_MODEL - mu * mu;
        s_mu = mu;
        s_rs = rsqrtf(var + 1e-5f);
    }
    __syncthreads();
    const float mu = s_mu, rs = s_rs;
    const float4 gg = ((const float4*)gamma)[tid];
    const float4 bb = ((const float4*)beta)[tid];
    float4 o;
    o.x = (v.x - mu) * rs * gg.x + bb.x;
    o.y = (v.y - mu) * rs * gg.y + bb.y;
    o.z = (v.z - mu) * rs * gg.z + bb.z;
    o.w = (v.w - mu) * rs * gg.w + bb.w;
    ((float4*)out)[(size_t)t * (D_MODEL / 4) + tid] = o;
}

// ---------------- launch -----------------------------------------------------
extern "C" void kernel_launch(void* const* d_in, const int* in_sizes, int n_in,
                              void* d_out, int out_size) {
    const float* x     = (const float*)d_in[0];
    const float* wr    = (const float*)d_in[1];
    const float* wg    = (const float*)d_in[2];
    const float* wu    = (const float*)d_in[3];
    const float* wd    = (const float*)d_in[4];
    const float* gamma = (const float*)d_in[5];
    const float* beta  = (const float*)d_in[6];
    float* out = (float*)d_out;

    zero_cnt_kernel<<<1, 32>>>();
    router_kernel<<<T_TOKENS, 256>>>(x, wr);
    dim3 g2(NPAIR / 128, D_FFN / 64, NE);
    gateup_kernel<<<g2, 256>>>(x, wg, wu);
    dim3 g3(NPAIR / 128, D_MODEL / 128, NE);
    down_kernel<<<g3, 256>>>(wd);
    combine_ln_kernel<<<T_TOKENS, 256>>>(gamma, beta, out);
}

// round 5
// speedup vs baseline: 1.9265x; 1.5698x over previous
#include <cuda_runtime.h>
#include <cuda_bf16.h>
#include <math.h>
#include <stdint.h>

#define D_MODEL 1024
#define D_FFN   2048
#define NE      8
#define T_TOKENS 4096
#define NPAIR   8192

// ---------------- scratch (device globals) ----------------------------------
__device__ int   g_cnt[NE];
__device__ int   g_pid[NE * NPAIR];
__device__ float g_wt [NE * NPAIR];
__device__ __nv_bfloat16 g_xhi[(size_t)T_TOKENS * D_MODEL];
__device__ __nv_bfloat16 g_xlo[(size_t)T_TOKENS * D_MODEL];
__device__ __nv_bfloat16 g_wghi[(size_t)NE * D_FFN * D_MODEL];
__device__ __nv_bfloat16 g_wglo[(size_t)NE * D_FFN * D_MODEL];
__device__ __nv_bfloat16 g_wuhi[(size_t)NE * D_FFN * D_MODEL];
__device__ __nv_bfloat16 g_wulo[(size_t)NE * D_FFN * D_MODEL];
__device__ __nv_bfloat16 g_wdhi[(size_t)NE * D_MODEL * D_FFN];
__device__ __nv_bfloat16 g_wdlo[(size_t)NE * D_MODEL * D_FFN];
__device__ __nv_bfloat16 g_Hhi[(size_t)NPAIR * D_FFN];
__device__ __nv_bfloat16 g_Hlo[(size_t)NPAIR * D_FFN];
__device__ float g_Y[(size_t)NPAIR * D_MODEL];

// ---------------- portable PTX helpers ---------------------------------------
__device__ __forceinline__ uint32_t smem_u32(const void* p) {
    uint32_t a;
    asm("{ .reg .u64 t; cvta.to.shared.u64 t, %1; cvt.u32.u64 %0, t; }" : "=r"(a) : "l"(p));
    return a;
}
#define CP_ASYNC(dst, src) \
    asm volatile("cp.async.cg.shared.global [%0], [%1], 16;" :: "r"(dst), "l"(src))
#define CP_COMMIT() asm volatile("cp.async.commit_group;" ::: "memory")
#define CP_WAIT(n)  asm volatile("cp.async.wait_group %0;" :: "n"(n) : "memory")

__device__ __forceinline__ uint32_t swz(uint32_t o) { return o ^ ((o >> 3) & 0x70); }

__device__ __forceinline__ void ldsm4(uint32_t r[4], uint32_t addr) {
    asm volatile("ldmatrix.sync.aligned.m8n8.x4.shared.b16 {%0,%1,%2,%3}, [%4];"
                 : "=r"(r[0]), "=r"(r[1]), "=r"(r[2]), "=r"(r[3]) : "r"(addr));
}
__device__ __forceinline__ void mma16816(float* c, const uint32_t a[4],
                                         uint32_t b0, uint32_t b1) {
    asm volatile(
        "mma.sync.aligned.m16n8k16.row.col.f32.bf16.bf16.f32 "
        "{%0,%1,%2,%3}, {%4,%5,%6,%7}, {%8,%9}, {%0,%1,%2,%3};"
        : "+f"(c[0]), "+f"(c[1]), "+f"(c[2]), "+f"(c[3])
        : "r"(a[0]), "r"(a[1]), "r"(a[2]), "r"(a[3]), "r"(b0), "r"(b1));
}

// ---------------- kernel 0: reset counters ----------------------------------
__global__ void zero_cnt_kernel() {
    if (threadIdx.x < NE) g_cnt[threadIdx.x] = 0;
}

// ---------------- kernel 1: router ------------------------------------------
__global__ __launch_bounds__(256) void router_kernel(const float* __restrict__ x,
                                                     const float* __restrict__ wr) {
    const int t = blockIdx.x;
    const int warp = threadIdx.x >> 5, lane = threadIdx.x & 31;
    __shared__ float logits[NE];
    const float* xr = x + (size_t)t * D_MODEL;
    const float* w  = wr + (size_t)warp * D_MODEL;
    float s = 0.f;
    #pragma unroll 8
    for (int i = lane; i < D_MODEL; i += 32) s += xr[i] * w[i];
    #pragma unroll
    for (int o = 16; o; o >>= 1) s += __shfl_xor_sync(0xffffffffu, s, o);
    if (lane == 0) logits[warp] = s;
    __syncthreads();
    if (threadIdx.x == 0) {
        int i0 = 0; float v0 = logits[0];
        #pragma unroll
        for (int e = 1; e < NE; e++) if (logits[e] > v0) { v0 = logits[e]; i0 = e; }
        int i1 = -1; float v1 = -1e30f;
        #pragma unroll
        for (int e = 0; e < NE; e++)
            if (e != i0 && logits[e] > v1) { v1 = logits[e]; i1 = e; }
        float ex = __expf(v1 - v0);
        float w0 = 1.f / (1.f + ex);
        float w1 = ex  / (1.f + ex);
        int s0 = atomicAdd(&g_cnt[i0], 1);
        g_pid[i0 * NPAIR + s0] = t * 2;     g_wt[i0 * NPAIR + s0] = w0;
        int s1 = atomicAdd(&g_cnt[i1], 1);
        g_pid[i1 * NPAIR + s1] = t * 2 + 1; g_wt[i1 * NPAIR + s1] = w1;
    }
}

// ---------------- bf16 hi/lo split ------------------------------------------
__global__ __launch_bounds__(256) void split_kernel(const float4* __restrict__ src,
                                                    int which, int n4) {
    __nv_bfloat16 *hi, *lo;
    switch (which) {
        case 0: hi = g_xhi;  lo = g_xlo;  break;
        case 1: hi = g_wghi; lo = g_wglo; break;
        case 2: hi = g_wuhi; lo = g_wulo; break;
        default: hi = g_wdhi; lo = g_wdlo; break;
    }
    union U4 { __nv_bfloat16 b[4]; uint2 u; };
    uint2* h2 = (uint2*)hi;
    uint2* l2 = (uint2*)lo;
    for (int i = blockIdx.x * blockDim.x + threadIdx.x; i < n4; i += gridDim.x * blockDim.x) {
        float4 v = src[i];
        U4 H, L;
        H.b[0] = __float2bfloat16(v.x); L.b[0] = __float2bfloat16(v.x - __bfloat162float(H.b[0]));
        H.b[1] = __float2bfloat16(v.y); L.b[1] = __float2bfloat16(v.y - __bfloat162float(H.b[1]));
        H.b[2] = __float2bfloat16(v.z); L.b[2] = __float2bfloat16(v.z - __bfloat162float(H.b[2]));
        H.b[3] = __float2bfloat16(v.w); L.b[3] = __float2bfloat16(v.w - __bfloat162float(H.b[3]));
        h2[i] = H.u;
        l2[i] = L.u;
    }
}

// =============================================================================
// gate+up GEMM via mma.sync. CTA: M=128 pairs, N=64 (gate and up), K chunk 64.
// Stage layout (64KB): Ahi@0 Alo@16K | Bghi@32K Bglo@40K Buhi@48K Bulo@56K
// 8 warps: wm = wid>>1 (m 32-block), wn = wid&1 (n 32-block). Warp tile 32x32.
// =============================================================================
#define GU_SMEM (1024 + 2 * 65536)
__global__ __launch_bounds__(256) void gateup_kernel() {
    const int e  = blockIdx.z;
    const int ne = g_cnt[e];
    const int m0 = blockIdx.x * 128;
    if (m0 >= ne) return;
    const int n0 = blockIdx.y * 64;

    extern __shared__ __align__(1024) char smem[];
    const uint32_t sb = smem_u32(smem);
    int* s_pid = (int*)smem;
    const int tid  = threadIdx.x;
    const int wid  = tid >> 5, lane = tid & 31;
    const int wm   = wid >> 1, wn = wid & 1;

    if (tid < 128) {
        int r = m0 + tid;
        s_pid[tid] = g_pid[e * NPAIR + (r < ne ? r : m0)];
    }
    __syncthreads();

    // cp.async geometry: A rows: 2 threads/row, 4 segs each; B rows: 4 thr/row, 2 segs
    const int rowA = tid >> 1, halfA = tid & 1;
    const int rowB = tid >> 2, segB0 = (tid & 3) * 2;
    const __nv_bfloat16* gxh = g_xhi + (size_t)(s_pid[rowA] >> 1) * D_MODEL + halfA * 32;
    const __nv_bfloat16* gxl = g_xlo + (size_t)(s_pid[rowA] >> 1) * D_MODEL + halfA * 32;
    const size_t boff = ((size_t)e * D_FFN + n0 + rowB) * D_MODEL + segB0 * 8;
    const __nv_bfloat16* gbgh = g_wghi + boff;
    const __nv_bfloat16* gbgl = g_wglo + boff;
    const __nv_bfloat16* gbuh = g_wuhi + boff;
    const __nv_bfloat16* gbul = g_wulo + boff;
    uint32_t oA[4], oB[2];
    #pragma unroll
    for (int j = 0; j < 4; ++j) oA[j] = swz((uint32_t)(rowA * 128 + halfA * 64 + j * 16));
    #pragma unroll
    for (int j = 0; j < 2; ++j) oB[j] = swz((uint32_t)(rowB * 128 + (segB0 + j) * 16));

#define GU_LOAD(kb, buf) do {                                                   \
        const uint32_t db = sb + 1024 + (buf) * 65536;                          \
        _Pragma("unroll") for (int j = 0; j < 4; ++j) {                         \
            CP_ASYNC(db +         oA[j], gxh + (kb) + j * 8);                   \
            CP_ASYNC(db + 16384 + oA[j], gxl + (kb) + j * 8);                   \
        }                                                                       \
        _Pragma("unroll") for (int j = 0; j < 2; ++j) {                         \
            CP_ASYNC(db + 32768 + oB[j], gbgh + (kb) + j * 8);                  \
            CP_ASYNC(db + 40960 + oB[j], gbgl + (kb) + j * 8);                  \
            CP_ASYNC(db + 49152 + oB[j], gbuh + (kb) + j * 8);                  \
            CP_ASYNC(db + 57344 + oB[j], gbul + (kb) + j * 8);                  \
        } } while (0)

    float ag[2][4][4], au[2][4][4];
    #pragma unroll
    for (int i = 0; i < 2; ++i)
        #pragma unroll
        for (int j = 0; j < 4; ++j)
            #pragma unroll
            for (int q = 0; q < 4; ++q) { ag[i][j][q] = 0.f; au[i][j][q] = 0.f; }

    const int NC = D_MODEL / 64;   // 16
    GU_LOAD(0, 0);
    CP_COMMIT();
    for (int ch = 0; ch < NC; ++ch) {
        if (ch + 1 < NC) { GU_LOAD((ch + 1) * 64, (ch + 1) & 1); CP_COMMIT(); CP_WAIT(1); }
        else             { CP_WAIT(0); }
        __syncthreads();
        const uint32_t Ab = sb + 1024 + (ch & 1) * 65536;
        const uint32_t Bb = Ab + 32768;
        #pragma unroll
        for (int s = 0; s < 4; ++s) {
            const int k0 = s * 16;
            uint32_t ah[2][4], al[2][4];
            #pragma unroll
            for (int i = 0; i < 2; ++i) {
                const uint32_t o = (uint32_t)((wm * 32 + i * 16 + (lane & 15)) * 128
                                              + (k0 + (lane >> 4) * 8) * 2);
                const uint32_t a = Ab + swz(o);
                ldsm4(ah[i], a);
                ldsm4(al[i], a + 16384);
            }
            // B: K-major [n][k] tile -> NON-trans ldmatrix, A-style addressing.
            // x4 covers 16 n-rows: r0=(n0-7,k0-7) r1=(n8-15,k0-7) r2=(n0-7,k8-15) r3=(n8-15,k8-15)
            uint32_t bg[2][4], bgl2[2][4], bu[2][4], bul2[2][4];
            #pragma unroll
            for (int j = 0; j < 2; ++j) {
                const uint32_t o = (uint32_t)((wn * 32 + j * 16 + (lane & 15)) * 128
                                              + (k0 + (lane >> 4) * 8) * 2);
                const uint32_t a = Bb + swz(o);
                ldsm4(bg[j],   a);
                ldsm4(bgl2[j], a + 8192);
                ldsm4(bu[j],   a + 16384);
                ldsm4(bul2[j], a + 24576);
            }
            #pragma unroll
            for (int i = 0; i < 2; ++i)
                #pragma unroll
                for (int j = 0; j < 2; ++j)
                    #pragma unroll
                    for (int h = 0; h < 2; ++h) {
                        float* cg = ag[i][j * 2 + h];
                        float* cu = au[i][j * 2 + h];
                        mma16816(cg, ah[i], bg[j][h],   bg[j][h + 2]);
                        mma16816(cg, ah[i], bgl2[j][h], bgl2[j][h + 2]);
                        mma16816(cg, al[i], bg[j][h],   bg[j][h + 2]);
                        mma16816(cu, ah[i], bu[j][h],   bu[j][h + 2]);
                        mma16816(cu, ah[i], bul2[j][h], bul2[j][h + 2]);
                        mma16816(cu, al[i], bu[j][h],   bu[j][h + 2]);
                    }
        }
        __syncthreads();
    }
#undef GU_LOAD

    // epilogue: SwiGLU, write H hi/lo (duplicate rows write identical data)
    #pragma unroll
    for (int i = 0; i < 2; ++i) {
        const int m1 = wm * 32 + i * 16 + (lane >> 2);
        const int m2 = m1 + 8;
        const int pid1 = s_pid[m1], pid2 = s_pid[m2];
        #pragma unroll
        for (int jn = 0; jn < 4; ++jn) {
            const int col = n0 + wn * 32 + jn * 8 + (lane & 3) * 2;
            const float* cg = ag[i][jn];
            const float* cu = au[i][jn];
            float h0 = (cg[0] / (1.f + __expf(-cg[0]))) * cu[0];
            float h1 = (cg[1] / (1.f + __expf(-cg[1]))) * cu[1];
            float h2 = (cg[2] / (1.f + __expf(-cg[2]))) * cu[2];
            float h3 = (cg[3] / (1.f + __expf(-cg[3]))) * cu[3];
            __nv_bfloat16 a0 = __float2bfloat16(h0), a1 = __float2bfloat16(h1);
            __nv_bfloat16 b0 = __float2bfloat16(h2), b1 = __float2bfloat16(h3);
            __nv_bfloat16 a0l = __float2bfloat16(h0 - __bfloat162float(a0));
            __nv_bfloat16 a1l = __float2bfloat16(h1 - __bfloat162float(a1));
            __nv_bfloat16 b0l = __float2bfloat16(h2 - __bfloat162float(b0));
            __nv_bfloat16 b1l = __float2bfloat16(h3 - __bfloat162float(b1));
            *(__nv_bfloat162*)&g_Hhi[(size_t)pid1 * D_FFN + col] = __nv_bfloat162(a0, a1);
            *(__nv_bfloat162*)&g_Hlo[(size_t)pid1 * D_FFN + col] = __nv_bfloat162(a0l, a1l);
            *(__nv_bfloat162*)&g_Hhi[(size_t)pid2 * D_FFN + col] = __nv_bfloat162(b0, b1);
            *(__nv_bfloat162*)&g_Hlo[(size_t)pid2 * D_FFN + col] = __nv_bfloat162(b0l, b1l);
        }
    }
}

// =============================================================================
// down GEMM via mma.sync. CTA: M=128 x N=128, K chunk 64 (x32).
// Stage (64KB): Ahi@0 Alo@16K Bhi@32K Blo@48K.
// 8 warps: wm = wid>>2 (m 64-block), wn = wid&3 (n 32-block). Warp tile 64x32.
// =============================================================================
#define DN_SMEM (1024 + 2 * 65536)
__global__ __launch_bounds__(256) void down_kernel() {
    const int e  = blockIdx.z;
    const int ne = g_cnt[e];
    const int m0 = blockIdx.x * 128;
    if (m0 >= ne) return;
    const int n0 = blockIdx.y * 128;

    extern __shared__ __align__(1024) char smem[];
    const uint32_t sb = smem_u32(smem);
    int*   s_pid = (int*)smem;
    float* s_w   = (float*)(smem + 512);
    const int tid  = threadIdx.x;
    const int wid  = tid >> 5, lane = tid & 31;
    const int wm   = wid >> 2, wn = wid & 3;

    if (tid < 128) {
        int r  = m0 + tid;
        int rr = (r < ne) ? r : m0;
        s_pid[tid] = g_pid[e * NPAIR + rr];
        s_w[tid]   = g_wt [e * NPAIR + rr];
    }
    __syncthreads();

    const int rowA = tid >> 1, halfA = tid & 1;
    const __nv_bfloat16* gah = g_Hhi + (size_t)s_pid[rowA] * D_FFN + halfA * 32;
    const __nv_bfloat16* gal = g_Hlo + (size_t)s_pid[rowA] * D_FFN + halfA * 32;
    const size_t boff = ((size_t)e * D_MODEL + n0 + rowA) * D_FFN + halfA * 32;
    const __nv_bfloat16* gbh = g_wdhi + boff;
    const __nv_bfloat16* gbl = g_wdlo + boff;
    uint32_t oA[4];
    #pragma unroll
    for (int j = 0; j < 4; ++j) oA[j] = swz((uint32_t)(rowA * 128 + halfA * 64 + j * 16));

#define DN_LOAD(kb, buf) do {                                                   \
        const uint32_t db = sb + 1024 + (buf) * 65536;                          \
        _Pragma("unroll") for (int j = 0; j < 4; ++j) {                         \
            CP_ASYNC(db +         oA[j], gah + (kb) + j * 8);                   \
            CP_ASYNC(db + 16384 + oA[j], gal + (kb) + j * 8);                   \
            CP_ASYNC(db + 32768 + oA[j], gbh + (kb) + j * 8);                   \
            CP_ASYNC(db + 49152 + oA[j], gbl + (kb) + j * 8);                   \
        } } while (0)

    float acc[4][4][4];
    #pragma unroll
    for (int i = 0; i < 4; ++i)
        #pragma unroll
        for (int j = 0; j < 4; ++j)
            #pragma unroll
            for (int q = 0; q < 4; ++q) acc[i][j][q] = 0.f;

    const int NC = D_FFN / 64;   // 32
    DN_LOAD(0, 0);
    CP_COMMIT();
    for (int ch = 0; ch < NC; ++ch) {
        if (ch + 1 < NC) { DN_LOAD((ch + 1) * 64, (ch + 1) & 1); CP_COMMIT(); CP_WAIT(1); }
        else             { CP_WAIT(0); }
        __syncthreads();
        const uint32_t Ab = sb + 1024 + (ch & 1) * 65536;
        const uint32_t Bb = Ab + 32768;
        #pragma unroll
        for (int s = 0; s < 4; ++s) {
            const int k0 = s * 16;
            uint32_t ah[4][4], al[4][4];
            #pragma unroll
            for (int i = 0; i < 4; ++i) {
                const uint32_t o = (uint32_t)((wm * 64 + i * 16 + (lane & 15)) * 128
                                              + (k0 + (lane >> 4) * 8) * 2);
                const uint32_t a = Ab + swz(o);
                ldsm4(ah[i], a);
                ldsm4(al[i], a + 16384);
            }
            // B: K-major -> non-trans ldmatrix, A-style addressing
            uint32_t bh[2][4], bl[2][4];
            #pragma unroll
            for (int j = 0; j < 2; ++j) {
                const uint32_t o = (uint32_t)((wn * 32 + j * 16 + (lane & 15)) * 128
                                              + (k0 + (lane >> 4) * 8) * 2);
                const uint32_t a = Bb + swz(o);
                ldsm4(bh[j], a);
                ldsm4(bl[j], a + 16384);
            }
            #pragma unroll
            for (int i = 0; i < 4; ++i)
                #pragma unroll
                for (int j = 0; j < 2; ++j)
                    #pragma unroll
                    for (int h = 0; h < 2; ++h) {
                        float* c = acc[i][j * 2 + h];
                        mma16816(c, ah[i], bh[j][h], bh[j][h + 2]);
                        mma16816(c, ah[i], bl[j][h], bl[j][h + 2]);
                        mma16816(c, al[i], bh[j][h], bh[j][h + 2]);
                    }
        }
        __syncthreads();
    }
#undef DN_LOAD

    #pragma unroll
    for (int i = 0; i < 4; ++i) {
        const int m1 = wm * 64 + i * 16 + (lane >> 2);
        const int m2 = m1 + 8;
        const int pid1 = s_pid[m1], pid2 = s_pid[m2];
        const float w1 = s_w[m1], w2 = s_w[m2];
        #pragma unroll
        for (int jn = 0; jn < 4; ++jn) {
            const int col = n0 + wn * 32 + jn * 8 + (lane & 3) * 2;
            const float* c = acc[i][jn];
            float2 v1 = { c[0] * w1, c[1] * w1 };
            float2 v2 = { c[2] * w2, c[3] * w2 };
            *(float2*)&g_Y[(size_t)pid1 * D_MODEL + col] = v1;
            *(float2*)&g_Y[(size_t)pid2 * D_MODEL + col] = v2;
        }
    }
}

// ---------------- kernel: combine pairs + LayerNorm --------------------------
__global__ __launch_bounds__(256) void combine_ln_kernel(const float* __restrict__ gamma,
                                                         const float* __restrict__ beta,
                                                         float* __restrict__ out) {
    const int t   = blockIdx.x;
    const int tid = threadIdx.x;
    const float4 a = ((const float4*)(g_Y + (size_t)(2 * t)     * D_MODEL))[tid];
    const float4 b = ((const float4*)(g_Y + (size_t)(2 * t + 1) * D_MODEL))[tid];
    float4 v = { a.x + b.x, a.y + b.y, a.z + b.z, a.w + b.w };

    float s  = v.x + v.y + v.z + v.w;
    float sq = v.x * v.x + v.y * v.y + v.z * v.z + v.w * v.w;
    #pragma unroll
    for (int o = 16; o; o >>= 1) {
        s  += __shfl_xor_sync(0xffffffffu, s,  o);
        sq += __shfl_xor_sync(0xffffffffu, sq, o);
    }
    __shared__ float rs_[8], rq_[8];
    __shared__ float s_mu, s_rs;
    if ((tid & 31) == 0) { rs_[tid >> 5] = s; rq_[tid >> 5] = sq; }
    __syncthreads();
    if (tid == 0) {
        float S = 0.f, Q = 0.f;
        #pragma unroll
        for (int i = 0; i < 8; i++) { S += rs_[i]; Q += rq_[i]; }
        float mu  = S / (float)D_MODEL;
        float var = Q / (float)D_MODEL - mu * mu;
        s_mu = mu;
        s_rs = rsqrtf(var + 1e-5f);
    }
    __syncthreads();
    const float mu = s_mu, rs = s_rs;
    const float4 gg = ((const float4*)gamma)[tid];
    const float4 bb = ((const float4*)beta)[tid];
    float4 o;
    o.x = (v.x - mu) * rs * gg.x + bb.x;
    o.y = (v.y - mu) * rs * gg.y + bb.y;
    o.z = (v.z - mu) * rs * gg.z + bb.z;
    o.w = (v.w - mu) * rs * gg.w + bb.w;
    ((float4*)out)[(size_t)t * (D_MODEL / 4) + tid] = o;
}

// ---------------- launch ------------------------------------------------------
extern "C" void kernel_launch(void* const* d_in, const int* in_sizes, int n_in,
                              void* d_out, int out_size) {
    const float* x     = (const float*)d_in[0];
    const float* wr    = (const float*)d_in[1];
    const float* wg    = (const float*)d_in[2];
    const float* wu    = (const float*)d_in[3];
    const float* wd    = (const float*)d_in[4];
    const float* gamma = (const float*)d_in[5];
    const float* beta  = (const float*)d_in[6];
    float* out = (float*)d_out;

    cudaFuncSetAttribute(gateup_kernel, cudaFuncAttributeMaxDynamicSharedMemorySize, GU_SMEM);
    cudaFuncSetAttribute(down_kernel,   cudaFuncAttributeMaxDynamicSharedMemorySize, DN_SMEM);

    zero_cnt_kernel<<<1, 32>>>();
    router_kernel<<<T_TOKENS, 256>>>(x, wr);

    const int nx4 = T_TOKENS * D_MODEL / 4;
    const int nw4 = NE * D_FFN * D_MODEL / 4;
    split_kernel<<<2048, 256>>>((const float4*)x,  0, nx4);
    split_kernel<<<4096, 256>>>((const float4*)wg, 1, nw4);
    split_kernel<<<4096, 256>>>((const float4*)wu, 2, nw4);
    split_kernel<<<4096, 256>>>((const float4*)wd, 3, nw4);

    dim3 g2(NPAIR / 128, D_FFN / 64, NE);
    gateup_kernel<<<g2, 256, GU_SMEM>>>();
    dim3 g3(NPAIR / 128, D_MODEL / 128, NE);
    down_kernel<<<g3, 256, DN_SMEM>>>();
    combine_ln_kernel<<<T_TOKENS, 256>>>(gamma, beta, out);
}